// round 1
// baseline (speedup 1.0000x reference)
#include <cuda_runtime.h>
#include <math.h>

#define SENT 64
#define WRD  32
#define DIM  300
#define HID  50

// scratch (device globals; no allocation)
__device__ float g_pre[2 * SENT * 160];   // [dir][s][gate*50+o], row stride 160
__device__ float g_hsum[128];             // [dir*64 + h], h<50 used

__device__ __forceinline__ float tanh_acc(float x) {
    float e = __expf(-2.0f * fabsf(x));
    float t = (1.0f - e) / (1.0f + e);
    return copysignf(t, x);
}
__device__ __forceinline__ float sigm(float x) {
    return 1.0f / (1.0f + __expf(-x));
}

// ---------------------------------------------------------------------------
// K1: per sentence -> window-mean trick -> rep[50] -> pre-activations
// ---------------------------------------------------------------------------
__global__ void __launch_bounds__(256, 1)
k1_rep_pre(const int* __restrict__ doc, const float* __restrict__ emb,
           const float* __restrict__ wl_w, const float* __restrict__ wl_b,
           const float* __restrict__ c1w, const float* __restrict__ c1b,
           const float* __restrict__ c2w, const float* __restrict__ c2b,
           const float* __restrict__ c3w, const float* __restrict__ c3b,
           const float* __restrict__ fiw, const float* __restrict__ fib,
           const float* __restrict__ ffw, const float* __restrict__ ffb,
           const float* __restrict__ fgw, const float* __restrict__ fgb,
           const float* __restrict__ biw, const float* __restrict__ bib,
           const float* __restrict__ bfw, const float* __restrict__ bfb,
           const float* __restrict__ bgw, const float* __restrict__ bgb)
{
    __shared__ float sV[6][304];   // 6 window-mean embedding vectors
    __shared__ float sM[6][52];    // window-mean of p (post word_linear)
    __shared__ float sRep[52];
    __shared__ int   sIdx[32];

    const int tid = threadIdx.x;
    const int s   = blockIdx.x;

    if (tid < 32) sIdx[tid] = doc[s * WRD + tid];
    __syncthreads();

    // Window means of embeddings: all 6 derive from Z and edge words 0,1,30,31.
    for (int d = tid; d < DIM; d += 256) {
        float z = 0.f, e0 = 0.f, e1 = 0.f, e30 = 0.f, e31 = 0.f;
        #pragma unroll
        for (int w = 0; w < 32; w++) {
            float v = __ldg(emb + (size_t)sIdx[w] * DIM + d);
            z += v;
            if (w == 0)  e0  = v;
            if (w == 1)  e1  = v;
            if (w == 30) e30 = v;
            if (w == 31) e31 = v;
        }
        sV[0][d] = z * (1.f / 32.f);
        sV[1][d] = (z - e31)       * (1.f / 31.f);
        sV[2][d] = (z - e0)        * (1.f / 31.f);
        sV[3][d] = (z - e30 - e31) * (1.f / 30.f);
        sV[4][d] = (z - e0  - e31) * (1.f / 30.f);
        sV[5][d] = (z - e0  - e1)  * (1.f / 30.f);
    }
    __syncthreads();

    // M[j][i] = wl_b[i] + <V[j], wl_w[i,:]>   (300 dots of length 300)
    for (int r = tid; r < 300; r += 256) {
        const int j = r / 50, i = r % 50;
        const float4* wr = (const float4*)(wl_w + i * DIM);
        const float4* vr = (const float4*)(&sV[j][0]);
        float a0 = 0.f, a1 = 0.f, a2 = 0.f, a3 = 0.f;
        #pragma unroll
        for (int t = 0; t < 75; t++) {
            float4 wv = __ldg(wr + t);
            float4 vv = vr[t];
            a0 = fmaf(wv.x, vv.x, a0);
            a1 = fmaf(wv.y, vv.y, a1);
            a2 = fmaf(wv.z, vv.z, a2);
            a3 = fmaf(wv.w, vv.w, a3);
        }
        sM[j][i] = (a0 + a1) + (a2 + a3) + wl_b[i];
    }
    __syncthreads();

    // rep[o] = mean of 3 tanh conv-branch means
    if (tid < 50) {
        const int o = tid;
        float a1 = c1b[o], a2 = c2b[o], a3 = c3b[o];
        #pragma unroll 10
        for (int i = 0; i < 50; i++) {
            a1 = fmaf(__ldg(c1w + o * 50 + i), sM[0][i], a1);
            const float* w2 = c2w + (o * 50 + i) * 2;
            a2 = fmaf(__ldg(w2 + 0), sM[1][i], a2);
            a2 = fmaf(__ldg(w2 + 1), sM[2][i], a2);
            const float* w3 = c3w + (o * 50 + i) * 3;
            a3 = fmaf(__ldg(w3 + 0), sM[3][i], a3);
            a3 = fmaf(__ldg(w3 + 1), sM[4][i], a3);
            a3 = fmaf(__ldg(w3 + 2), sM[5][i], a3);
        }
        sRep[o] = (tanh_acc(a1) + tanh_acc(a2) + tanh_acc(a3)) * (1.f / 3.f);
    }
    __syncthreads();

    // pre[dir][s][gate*50+o] = bias + W[:, :50] @ rep   (parallelizable part of the scan)
    for (int r = tid; r < 300; r += 256) {
        const int dir = r / 150, q = r % 150;
        const int gate = q / 50, o = q % 50;
        const float* Wg; const float* Bg;
        if (dir == 0) { Wg = gate == 0 ? fiw : gate == 1 ? ffw : fgw;
                        Bg = gate == 0 ? fib : gate == 1 ? ffb : fgb; }
        else          { Wg = gate == 0 ? biw : gate == 1 ? bfw : bgw;
                        Bg = gate == 0 ? bib : gate == 1 ? bfb : bgb; }
        float acc = Bg[o];
        #pragma unroll 10
        for (int i = 0; i < 50; i++)
            acc = fmaf(__ldg(Wg + o * 100 + i), sRep[i], acc);
        g_pre[(dir * SENT + s) * 160 + q] = acc;
    }
}

// ---------------------------------------------------------------------------
// K2: serial gated scan. One block per direction. Weights register-resident,
// h ping-ponged in shared, ONE barrier per step.
// Thread map: h = tid>>2, part p = tid&3 splits the 50-dim h-dot into
// chunks {13,13,12,12}; each thread computes all 3 gates (ILP), quad-shuffle
// reduce, part-0 thread applies activations + recurrence.
// ---------------------------------------------------------------------------
__global__ void __launch_bounds__(256, 1)
k2_scan(const float* __restrict__ fiw, const float* __restrict__ ffw,
        const float* __restrict__ fgw, const float* __restrict__ biw,
        const float* __restrict__ bfw, const float* __restrict__ bgw)
{
    __shared__ float sPre[SENT][152];
    __shared__ float sH[2][52];

    const int tid = threadIdx.x;
    const int dir = blockIdx.x;

    for (int k = tid; k < SENT * 150; k += 256) {
        int s = k / 150, q = k % 150;
        sPre[s][q] = g_pre[(dir * SENT + s) * 160 + q];
    }
    if (tid < 104) sH[tid / 52][tid % 52] = 0.f;  // h0 = 0, incl. pad

    const int p = tid & 3;
    const int h = tid >> 2;
    const bool act = (h < 50);
    const int hc = act ? h : 49;
    const int j0 = (p < 2) ? p * 13 : 26 + (p - 2) * 12;
    const int jn = (p < 2) ? 13 : 12;

    const float* Wi = dir ? biw : fiw;
    const float* Wf = dir ? bfw : ffw;
    const float* Wg = dir ? bgw : fgw;

    float wi[13], wf[13], wg[13];
    #pragma unroll
    for (int k = 0; k < 13; k++) {
        const bool ok = act && (k < jn);
        const int idx = hc * 100 + 50 + j0 + k;   // h-columns of W
        wi[k] = ok ? __ldg(Wi + idx) : 0.f;
        wf[k] = ok ? __ldg(Wf + idx) : 0.f;
        wg[k] = ok ? __ldg(Wg + idx) : 0.f;
    }

    float hsum = 0.f;
    int cur = 0;
    __syncthreads();

    for (int s = 0; s < SENT; s++) {
        const int sp = dir ? (63 - s) : s;   // backward scan consumes reversed rep
        float a0 = 0.f, a1 = 0.f, a2 = 0.f;
        #pragma unroll
        for (int k = 0; k < 13; k++) {
            float hj = sH[cur][j0 + k];      // j0+k <= 50 (pad slot is 0)
            a0 = fmaf(wi[k], hj, a0);
            a1 = fmaf(wf[k], hj, a1);
            a2 = fmaf(wg[k], hj, a2);
        }
        a0 += __shfl_xor_sync(0xffffffffu, a0, 1);
        a1 += __shfl_xor_sync(0xffffffffu, a1, 1);
        a2 += __shfl_xor_sync(0xffffffffu, a2, 1);
        a0 += __shfl_xor_sync(0xffffffffu, a0, 2);
        a1 += __shfl_xor_sync(0xffffffffu, a1, 2);
        a2 += __shfl_xor_sync(0xffffffffu, a2, 2);

        if (p == 0 && act) {
            float iv = sigm(a0 + sPre[sp][h]);
            float fv = sigm(a1 + sPre[sp][50 + h]);
            float gv = tanh_acc(a2 + sPre[sp][100 + h]);
            float hn = tanh_acc(fmaf(fv, sH[cur][h], iv * gv));
            sH[cur ^ 1][h] = hn;   // write other buffer: single barrier suffices
            hsum += hn;
        }
        __syncthreads();
        cur ^= 1;
    }

    if (p == 0 && act) g_hsum[dir * 64 + h] = hsum;
}

// ---------------------------------------------------------------------------
// K3: logits + softmax (one warp)
// ---------------------------------------------------------------------------
__global__ void k3_out(const float* __restrict__ out_w,
                       const float* __restrict__ out_b,
                       float* __restrict__ out)
{
    const int lane = threadIdx.x;
    float lg[5];
    #pragma unroll
    for (int c = 0; c < 5; c++) {
        float acc = 0.f;
        for (int j = lane; j < 100; j += 32) {
            float g = ((j < 50) ? g_hsum[j] : g_hsum[64 + j - 50]) * (1.f / 64.f);
            acc = fmaf(__ldg(out_w + c * 100 + j), g, acc);
        }
        #pragma unroll
        for (int off = 16; off; off >>= 1)
            acc += __shfl_xor_sync(0xffffffffu, acc, off);
        lg[c] = acc + out_b[c];
    }
    float m = lg[0];
    #pragma unroll
    for (int c = 1; c < 5; c++) m = fmaxf(m, lg[c]);
    float e[5], sum = 0.f;
    #pragma unroll
    for (int c = 0; c < 5; c++) { e[c] = __expf(lg[c] - m); sum += e[c]; }
    float inv = 1.f / sum;
    if (lane < 5) out[lane] = e[lane] * inv;
}

// ---------------------------------------------------------------------------
extern "C" void kernel_launch(void* const* d_in, const int* in_sizes, int n_in,
                              void* d_out, int out_size)
{
    const int*   doc  = (const int*)  d_in[0];
    const float* emb  = (const float*)d_in[1];
    const float* wl_w = (const float*)d_in[2];
    const float* wl_b = (const float*)d_in[3];
    const float* c1w  = (const float*)d_in[4];
    const float* c1b  = (const float*)d_in[5];
    const float* c2w  = (const float*)d_in[6];
    const float* c2b  = (const float*)d_in[7];
    const float* c3w  = (const float*)d_in[8];
    const float* c3b  = (const float*)d_in[9];
    const float* fiw  = (const float*)d_in[10];
    const float* fib  = (const float*)d_in[11];
    const float* ffw  = (const float*)d_in[12];
    const float* ffb  = (const float*)d_in[13];
    const float* fgw  = (const float*)d_in[14];
    const float* fgb  = (const float*)d_in[15];
    const float* biw  = (const float*)d_in[16];
    const float* bib  = (const float*)d_in[17];
    const float* bfw  = (const float*)d_in[18];
    const float* bfb  = (const float*)d_in[19];
    const float* bgw  = (const float*)d_in[20];
    const float* bgb  = (const float*)d_in[21];
    const float* outw = (const float*)d_in[22];
    const float* outb = (const float*)d_in[23];

    k1_rep_pre<<<SENT, 256>>>(doc, emb, wl_w, wl_b, c1w, c1b, c2w, c2b, c3w, c3b,
                              fiw, fib, ffw, ffb, fgw, fgb,
                              biw, bib, bfw, bfb, bgw, bgb);
    k2_scan<<<2, 256>>>(fiw, ffw, fgw, biw, bfw, bgw);
    k3_out<<<1, 32>>>(outw, outb, (float*)d_out);
}